// round 13
// baseline (speedup 1.0000x reference)
#include <cuda_runtime.h>

#define BB   64
#define TT   128
#define HH   256
#define INN  256
#define VV   256
#define NDLY 32
#define BH   (BB*HH)
#define GRID 128
#define NTHR 1024
#define BSTR 66   // Bsd row stride in ull (even -> 16B-aligned pair loads)
typedef unsigned long long ull;

__device__ float    g_cw[NDLY*HH*INN];
__device__ float    g_xw[BB*TT*HH];
__device__ float    g_wa1[INN*HH];
__device__ ull      g_weT2[(HH/2)*VV];     // [h2][v] packed {w[v][2h2], w[v][2h2+1]}
__device__ float    g_hist[BB*NDLY*HH];
__device__ float    g_partial[NDLY*BB*HH];
__device__ unsigned g_keys[2*BB];
__device__ int      g_tau[BB], g_done[BB], g_stepsA[BB], g_curIdx[BB];
__device__ unsigned g_cnt1[8*32];          // 8 group counters, 128B apart
__device__ unsigned g_cnt2;
__device__ unsigned g_phase;

// ---- packed f32x2 helpers ----
__device__ __forceinline__ ull pkf2(float lo, float hi) {
    ull r; asm("mov.b64 %0, {%1, %2};" : "=l"(r) : "f"(lo), "f"(hi)); return r;
}
__device__ __forceinline__ float2 upkf2(ull v) {
    float2 r; asm("mov.b64 {%0, %1}, %2;" : "=f"(r.x), "=f"(r.y) : "l"(v)); return r;
}
__device__ __forceinline__ ull ffma2(ull a, ull b, ull c) {
    ull d; asm("fma.rn.f32x2 %0, %1, %2, %3;" : "=l"(d) : "l"(a), "l"(b), "l"(c));
    return d;
}

// XLA/Eigen f32 tanh
__device__ __forceinline__ float xla_tanh(float x) {
    if (fabsf(x) < 0.0004f) return x;
    float cx = fminf(fmaxf(x, -7.90531110763549805f), 7.90531110763549805f);
    float x2 = cx * cx;
    float p = fmaf(x2, -2.76076847742355e-16f, 2.00018790482477e-13f);
    p = fmaf(x2, p, -8.60467152213735e-11f);
    p = fmaf(x2, p,  5.12229709037114e-08f);
    p = fmaf(x2, p,  1.48572235717979e-05f);
    p = fmaf(x2, p,  6.37261928875436e-04f);
    p = fmaf(x2, p,  4.89352455891786e-03f);
    p = cx * p;
    float q = fmaf(x2, 1.19825839466702e-06f, 1.18534705686654e-04f);
    q = fmaf(x2, q, 2.26843463243900e-03f);
    q = fmaf(x2, q, 4.89352518554385e-03f);
    return p / q;
}

__device__ __forceinline__ void tf2x32(unsigned k0, unsigned k1,
                                       unsigned x0, unsigned x1,
                                       unsigned &o0, unsigned &o1) {
    unsigned ks2 = k0 ^ k1 ^ 0x1BD11BDAu;
    x0 += k0; x1 += k1;
#define TF_R(r) { x0 += x1; x1 = (x1 << (r)) | (x1 >> (32 - (r))); x1 ^= x0; }
    TF_R(13) TF_R(15) TF_R(26) TF_R(6)
    x0 += k1;  x1 += ks2 + 1u;
    TF_R(17) TF_R(29) TF_R(16) TF_R(24)
    x0 += ks2; x1 += k0 + 2u;
    TF_R(13) TF_R(15) TF_R(26) TF_R(6)
    x0 += k0;  x1 += k1 + 3u;
    TF_R(17) TF_R(29) TF_R(16) TF_R(24)
    x0 += k1;  x1 += ks2 + 4u;
    TF_R(13) TF_R(15) TF_R(26) TF_R(6)
    x0 += ks2; x1 += k0 + 5u;
#undef TF_R
    o0 = x0; o1 = x1;
}

// R9-style tree grid barrier (empirically best): relaxed atomics + threadfence
__device__ __forceinline__ void gsync(unsigned &ph) {
    __syncthreads();
    if (threadIdx.x == 0) {
        __threadfence();
        if (atomicAdd(&g_cnt1[(blockIdx.x >> 4) * 32], 1u) == 15u) {
            if (atomicAdd(&g_cnt2, 1u) == 7u) {
                g_cnt2 = 0u;
#pragma unroll
                for (int i = 0; i < 8; i++) g_cnt1[i * 32] = 0u;
                __threadfence();
                *(volatile unsigned*)&g_phase = ph + 1u;
            }
        }
        while (*(volatile unsigned*)&g_phase < ph + 1u) {}
        __threadfence();
    }
    ph++;
    __syncthreads();
}

// setup kernel 1: cw build + state init + PRNG child keys (merged)
__global__ void build_cw_kernel(const float* __restrict__ lateral,
                                const float* __restrict__ tau) {
    int i = blockIdx.x * 256 + threadIdx.x;
    int dd = i >> 16;
    int hi = i & 65535;
    const float INV = 0.0625f, INV2 = 0.0625f * 0.0625f;
    float tc = fminf(fmaxf(tau[hi], 1.0f), 32.0f);
    float t1 = ((float)(dd + 1) - tc) * INV2;
    float c  = fmaxf(0.0f, INV - fabsf(t1));
    g_cw[i] = c * lateral[hi];

    if (i < BB * NDLY * HH) g_hist[i] = 0.0f;
    if (i < BB) {
        g_tau[i] = 0; g_done[i] = 0; g_stepsA[i] = 0; g_curIdx[i] = -1;
        unsigned o0, o1;
        tf2x32(0u, 42u, 0u, (unsigned)i, o0, o1);
        g_keys[2 * i]     = o0;
        g_keys[2 * i + 1] = o1;
    }
    if (i < 8 * 32) g_cnt1[i] = 0u;
    if (i == 0) { g_cnt2 = 0u; g_phase = 0u; }
}

__global__ void build_aux_kernel(const float* __restrict__ w_aff,
                                 const float* __restrict__ b_aff,
                                 const float* __restrict__ w_eff) {
    int i = blockIdx.x * 256 + threadIdx.x;        // 65536
    int a = i / HH, h2a = i % HH;
    g_wa1[i] = w_aff[h2a * INN + a] + b_aff[h2a];
    if (i < (HH / 2) * VV) {
        int h2 = i / VV, v = i % VV;
        g_weT2[i] = pkf2(w_eff[v * HH + 2 * h2], w_eff[v * HH + 2 * h2 + 1]);
    }
}

// xw[m][h] = sum_i x[m][i]*w_aff[h][i] + b_aff[h]
__global__ __launch_bounds__(256) void xw_gemm_kernel(
        const float* __restrict__ x, const float* __restrict__ w_aff,
        const float* __restrict__ b_aff) {
    __shared__ float As[32][65], Ws[32][65];
    int m0 = blockIdx.x * 64, h0 = blockIdx.y * 64;
    int tid = threadIdx.x, tx = tid % 16, ty = tid / 16;
    float acc[4][4] = {{0}};
    for (int k0 = 0; k0 < INN; k0 += 32) {
        int r = tid >> 2, kq = tid & 3;
#pragma unroll
        for (int j = 0; j < 8; j++) {
            As[kq * 8 + j][r] = x[(size_t)(m0 + r) * INN + k0 + kq * 8 + j];
            Ws[kq * 8 + j][r] = w_aff[(h0 + r) * INN + k0 + kq * 8 + j];
        }
        __syncthreads();
#pragma unroll
        for (int k = 0; k < 32; k++) {
            float av[4], bv[4];
#pragma unroll
            for (int u = 0; u < 4; u++) av[u] = As[k][ty * 4 + u];
#pragma unroll
            for (int v = 0; v < 4; v++) bv[v] = Ws[k][tx * 4 + v];
#pragma unroll
            for (int u = 0; u < 4; u++)
#pragma unroll
                for (int v = 0; v < 4; v++)
                    acc[u][v] = fmaf(av[u], bv[v], acc[u][v]);
        }
        __syncthreads();
    }
#pragma unroll
    for (int u = 0; u < 4; u++)
#pragma unroll
        for (int v = 0; v < 4; v++) {
            int m = m0 + ty * 4 + u, h = h0 + tx * 4 + v;
            g_xw[(size_t)m * HH + h] = acc[u][v] + b_aff[h];
        }
}

// ---------------- persistent step kernel (1024 threads) ---------------------
__global__ __launch_bounds__(NTHR) void persistent_kernel(
        const int* __restrict__ lengths, const float* __restrict__ b_eff,
        float* __restrict__ out, int N, int writeSteps) {
    extern __shared__ ull dynsmem[];
    ull* Asd  = dynsmem;                 // [256 k][32]: hgg -> pair {h0+2hgg, +1}
    ull* Bsd0 = dynsmem + 256 * 32;      // [32 k][BSTR]: b -> dup {v,v}
    ull* Bsd1 = Bsd0 + 32 * BSTR;
    __shared__ int   rowOff[BB];
    __shared__ __align__(16) float sh_hdel[HH];
    __shared__ float parth[4][HH];
    __shared__ float ypart[4][VV];
    __shared__ float sval[VV];
    __shared__ int   sidx[VV];

    int tid = threadIdx.x, cta = blockIdx.x;
    int dd = cta >> 2, hb = cta & 3, h0 = hb * 64;
    int hgg = tid & 31, bg = tid >> 5;   // K1: h = h0+2hgg,+1 ; b = 2bg, 2bg+1
    int rb = tid >> 3, kq = tid & 7;     // B loader (tid<512): batch rb, k-oct kq
    int qa = tid >> 8, hq = tid & 255;   // K2 quarter split

    // one-time: pack cw tile into smem as h-pairs [k][hgg]
    {
        const float* cwd = g_cw + (size_t)dd * HH * INN;
        for (int idx = tid; idx < 256 * 32; idx += NTHR) {
            int k = idx >> 5, p = idx & 31;
            int h = h0 + p * 2;
            Asd[idx] = pkf2(cwd[(size_t)h * INN + k], cwd[(size_t)(h + 1) * INN + k]);
        }
    }
    __syncthreads();

    int lenb = (cta < BB) ? lengths[cta] : 0;
    unsigned ph = 0;
    int TS = TT + 9 + N;

    for (int step = 0; step < TS; step++) {
        // ---- K1 ----
        if (tid < BB) {
            int tb = __ldcg(&g_tau[tid]);
            rowOff[tid] = tid * (NDLY * HH) + (((tb - (dd + 1)) & 31) * HH);
        }
        __syncthreads();
        ull a0 = 0ull, a1 = 0ull;
        int brow = (tid < 512) ? rowOff[rb] : 0;
        if (tid < 512) {
            float4 bv = __ldcg((const float4*)(g_hist + brow + kq * 4));
            Bsd0[(kq * 4 + 0) * BSTR + rb] = pkf2(bv.x, bv.x);
            Bsd0[(kq * 4 + 1) * BSTR + rb] = pkf2(bv.y, bv.y);
            Bsd0[(kq * 4 + 2) * BSTR + rb] = pkf2(bv.z, bv.z);
            Bsd0[(kq * 4 + 3) * BSTR + rb] = pkf2(bv.w, bv.w);
        }
        __syncthreads();
#pragma unroll
        for (int c = 0; c < 8; c++) {
            const ull* cur = (c & 1) ? Bsd1 : Bsd0;
            float4 bnext;
            if (tid < 512 && c < 7)
                bnext = __ldcg((const float4*)(g_hist + brow + (c + 1) * 32 + kq * 4));
            const ull* ab = Asd + (size_t)c * 32 * 32;
#pragma unroll
            for (int k = 0; k < 32; k++) {
                ull A = ab[k * 32 + hgg];
                ulonglong2 Bp = *(const ulonglong2*)(cur + k * BSTR + bg * 2);
                a0 = ffma2(A, Bp.x, a0);
                a1 = ffma2(A, Bp.y, a1);
            }
            if (tid < 512 && c < 7) {
                ull* nxt = (c & 1) ? Bsd0 : Bsd1;
                nxt[(kq * 4 + 0) * BSTR + rb] = pkf2(bnext.x, bnext.x);
                nxt[(kq * 4 + 1) * BSTR + rb] = pkf2(bnext.y, bnext.y);
                nxt[(kq * 4 + 2) * BSTR + rb] = pkf2(bnext.z, bnext.z);
                nxt[(kq * 4 + 3) * BSTR + rb] = pkf2(bnext.w, bnext.w);
            }
            __syncthreads();
        }
        {
            float* P = g_partial + (size_t)dd * BH;
            float2 v0 = upkf2(a0), v1 = upkf2(a1);
            *(float2*)(P + (size_t)(bg * 2 + 0) * HH + h0 + hgg * 2) = v0;
            *(float2*)(P + (size_t)(bg * 2 + 1) * HH + h0 + hgg * 2) = v1;
        }
        gsync(ph);

        // ---- K2 ----
        if (cta < BB) {
            int b = cta;
            // quarter-split partial reduce: quarter qa sums s = qa*8+7 .. qa*8
            {
                float ps = 0.0f;
                int sbase = qa * 8;
#pragma unroll
                for (int s = 7; s >= 0; --s)
                    ps += __ldcg(&g_partial[(size_t)(sbase + s) * BH + b * HH + hq]);
                parth[qa][hq] = ps;
            }
            __syncthreads();

            if (step < TT) {
                if (tid < HH) {
                    float acc2 = ((parth[3][tid] + parth[2][tid]) +
                                  parth[1][tid]) + parth[0][tid];
                    int t = step;
                    float hvv = xla_tanh(g_xw[(size_t)(b * TT + t) * HH + tid] + acc2);
                    if (t < lenb) {
                        g_hist[b * (NDLY * HH) + (t & 31) * HH + tid] = hvv;
                        if (tid == 0) g_tau[b] = t + 1;
                    }
                }
            } else {
                int g = step - TT;
                int ci = g_curIdx[b], myTau = g_tau[b], myDone = g_done[b];
                int mySteps = g_stepsA[b];

                if (tid < HH)
                    sh_hdel[tid] = ((parth[3][tid] + parth[2][tid]) +
                                    parth[1][tid]) + parth[0][tid];
                __syncthreads();

                // logits matvec quarter: h2 in [qa*32, qa*32+32)
                {
                    const ull* hdl = (const ull*)sh_hdel;
                    int h2b = qa * 32;
                    ull ya = 0ull, yb = 0ull;
#pragma unroll 4
                    for (int j = 0; j < 32; j += 2) {
                        ya = ffma2(g_weT2[(size_t)(h2b + j) * VV + hq],     hdl[h2b + j],     ya);
                        yb = ffma2(g_weT2[(size_t)(h2b + j + 1) * VV + hq], hdl[h2b + j + 1], yb);
                    }
                    float2 pa = upkf2(ya), pb = upkf2(yb);
                    ypart[qa][hq] = (pa.x + pa.y) + (pb.x + pb.y);
                }
                __syncthreads();

                float y = 0.0f;
                if (tid < VV) {
                    y = (((ypart[3][tid] + ypart[2][tid]) + ypart[1][tid]) +
                         ypart[0][tid]) + b_eff[tid];

                    unsigned kv = (g < 9) ? (unsigned)g : (unsigned)(1000 + (g - 9));
                    unsigned f0, f1;
                    tf2x32(g_keys[2 * b], g_keys[2 * b + 1], 0u, kv, f0, f1);
                    unsigned o0, o1;
                    tf2x32(f0, f1, 0u, (unsigned)tid, o0, o1);
                    unsigned bits = o0 ^ o1;

                    const float TINY = 1.17549435e-38f;
                    float fm = __uint_as_float((bits >> 9) | 0x3F800000u) - 1.0f;
                    float uu = fmaxf(TINY, fm * (1.0f - TINY) + TINY);
                    float gum = -logf(-logf(uu));

                    sval[tid] = y + gum; sidx[tid] = tid;
                }
                __syncthreads();
                for (int off = 128; off > 0; off >>= 1) {
                    if (tid < off) {
                        float v2 = sval[tid + off]; int i2 = sidx[tid + off];
                        if (v2 > sval[tid] || (v2 == sval[tid] && i2 < sidx[tid])) {
                            sval[tid] = v2; sidx[tid] = i2;
                        }
                    }
                    __syncthreads();
                }
                int amax = sidx[0];

                if (tid < HH) {
                    float xin = (ci < 0) ? g_xw[(size_t)(b * TT + (lenb - 1)) * HH + tid]
                                         : g_wa1[ci * HH + tid];
                    float hvv = xla_tanh(xin + sh_hdel[tid]);

                    bool thinkPh = (g < 9);
                    bool adv = thinkPh ? (myDone == 0) : true;
                    if (adv) g_hist[b * (NDLY * HH) + (myTau & 31) * HH + tid] = hvv;

                    if (!thinkPh) {
                        int k = g - 9;
                        if (tid < VV - 1)
                            out[((size_t)b * N + k) * (VV - 1) + tid] = y;
                    }
                    if (tid == 0) {
                        if (thinkPh) {
                            int nst = mySteps + (myDone ? 0 : 1);
                            int nd = (myDone || amax == (VV - 1) || nst > 8) ? 1 : 0;
                            g_stepsA[b] = nst; g_done[b] = nd;
                            if (!myDone) { g_tau[b] = myTau + 1; g_curIdx[b] = amax; }
                            if (g == 8 && writeSteps)
                                out[(size_t)BB * N * (VV - 1) + b] = (float)nst;
                        } else {
                            g_tau[b] = myTau + 1; g_curIdx[b] = amax;
                        }
                    }
                }
            }
        }
        gsync(ph);
    }
}

extern "C" void kernel_launch(void* const* d_in, const int* in_sizes, int n_in,
                              void* d_out, int out_size) {
    const float* x       = (const float*)d_in[0];
    const float* w_aff   = (const float*)d_in[1];
    const float* b_aff   = (const float*)d_in[2];
    const float* lateral = (const float*)d_in[3];
    const float* tau     = (const float*)d_in[4];
    const float* w_eff   = (const float*)d_in[5];
    const float* b_eff   = (const float*)d_in[6];
    const int*   lengths = (const int*)d_in[7];
    (void)n_in; (void)in_sizes;
    float* out = (float*)d_out;

    int Vm1 = VV - 1;
    int N, writeSteps;
    if (out_size % (BB * Vm1) == 0) { N = out_size / (BB * Vm1); writeSteps = 0; }
    else { N = (out_size - BB) / (BB * Vm1); writeSteps = 1; }

    int dynBytes = (256 * 32 + 2 * 32 * BSTR) * (int)sizeof(ull);  // 99328
    cudaFuncSetAttribute(persistent_kernel,
                         cudaFuncAttributeMaxDynamicSharedMemorySize, dynBytes);

    build_cw_kernel<<<(NDLY * HH * INN) / 256, 256>>>(lateral, tau);
    build_aux_kernel<<<(INN * HH) / 256, 256>>>(w_aff, b_aff, w_eff);
    xw_gemm_kernel<<<dim3((BB * TT) / 64, HH / 64), 256>>>(x, w_aff, b_aff);

    persistent_kernel<<<GRID, NTHR, dynBytes>>>(lengths, b_eff, out, N, writeSteps);
}

// round 14
// speedup vs baseline: 1.2972x; 1.2972x over previous
#include <cuda_runtime.h>

#define BB   64
#define TT   128
#define HH   256
#define INN  256
#define VV   256
#define NDLY 32
#define BH   (BB*HH)
#define GRID 128
#define NTHR 512
typedef unsigned long long ull;

__device__ float    g_cw[NDLY*HH*INN];
__device__ float    g_xw[BB*TT*HH];
__device__ float    g_wa1[INN*HH];
__device__ ull      g_weT2[(HH/2)*VV];     // [h2][v] packed {w[v][2h2], w[v][2h2+1]}
__device__ float    g_hist[BB*NDLY*HH];
__device__ float    g_partial[NDLY*BB*HH];
__device__ unsigned g_keys[2*BB];
__device__ int      g_tau[BB], g_done[BB], g_stepsA[BB], g_curIdx[BB];
__device__ unsigned g_cnt1[8*32];          // 8 group counters, 128B apart
__device__ unsigned g_cnt2;
__device__ unsigned g_phase;

// ---- packed f32x2 helpers ----
__device__ __forceinline__ ull pkf2(float lo, float hi) {
    ull r; asm("mov.b64 %0, {%1, %2};" : "=l"(r) : "f"(lo), "f"(hi)); return r;
}
__device__ __forceinline__ float2 upkf2(ull v) {
    float2 r; asm("mov.b64 {%0, %1}, %2;" : "=f"(r.x), "=f"(r.y) : "l"(v)); return r;
}
__device__ __forceinline__ ull ffma2(ull a, ull b, ull c) {
    ull d; asm("fma.rn.f32x2 %0, %1, %2, %3;" : "=l"(d) : "l"(a), "l"(b), "l"(c));
    return d;
}

// XLA/Eigen f32 tanh
__device__ __forceinline__ float xla_tanh(float x) {
    if (fabsf(x) < 0.0004f) return x;
    float cx = fminf(fmaxf(x, -7.90531110763549805f), 7.90531110763549805f);
    float x2 = cx * cx;
    float p = fmaf(x2, -2.76076847742355e-16f, 2.00018790482477e-13f);
    p = fmaf(x2, p, -8.60467152213735e-11f);
    p = fmaf(x2, p,  5.12229709037114e-08f);
    p = fmaf(x2, p,  1.48572235717979e-05f);
    p = fmaf(x2, p,  6.37261928875436e-04f);
    p = fmaf(x2, p,  4.89352455891786e-03f);
    p = cx * p;
    float q = fmaf(x2, 1.19825839466702e-06f, 1.18534705686654e-04f);
    q = fmaf(x2, q, 2.26843463243900e-03f);
    q = fmaf(x2, q, 4.89352518554385e-03f);
    return p / q;
}

__device__ __forceinline__ void tf2x32(unsigned k0, unsigned k1,
                                       unsigned x0, unsigned x1,
                                       unsigned &o0, unsigned &o1) {
    unsigned ks2 = k0 ^ k1 ^ 0x1BD11BDAu;
    x0 += k0; x1 += k1;
#define TF_R(r) { x0 += x1; x1 = (x1 << (r)) | (x1 >> (32 - (r))); x1 ^= x0; }
    TF_R(13) TF_R(15) TF_R(26) TF_R(6)
    x0 += k1;  x1 += ks2 + 1u;
    TF_R(17) TF_R(29) TF_R(16) TF_R(24)
    x0 += ks2; x1 += k0 + 2u;
    TF_R(13) TF_R(15) TF_R(26) TF_R(6)
    x0 += k0;  x1 += k1 + 3u;
    TF_R(17) TF_R(29) TF_R(16) TF_R(24)
    x0 += k1;  x1 += ks2 + 4u;
    TF_R(13) TF_R(15) TF_R(26) TF_R(6)
    x0 += ks2; x1 += k0 + 5u;
#undef TF_R
    o0 = x0; o1 = x1;
}

// R9-style tree grid barrier (empirically best): relaxed atomics + threadfence
__device__ __forceinline__ void gsync(unsigned &ph) {
    __syncthreads();
    if (threadIdx.x == 0) {
        __threadfence();
        if (atomicAdd(&g_cnt1[(blockIdx.x >> 4) * 32], 1u) == 15u) {
            if (atomicAdd(&g_cnt2, 1u) == 7u) {
                g_cnt2 = 0u;
#pragma unroll
                for (int i = 0; i < 8; i++) g_cnt1[i * 32] = 0u;
                __threadfence();
                *(volatile unsigned*)&g_phase = ph + 1u;
            }
        }
        while (*(volatile unsigned*)&g_phase < ph + 1u) {}
        __threadfence();
    }
    ph++;
    __syncthreads();
}

// setup kernel 1: cw build + state init + PRNG child keys (merged)
__global__ void build_cw_kernel(const float* __restrict__ lateral,
                                const float* __restrict__ tau) {
    int i = blockIdx.x * 256 + threadIdx.x;
    int dd = i >> 16;
    int hi = i & 65535;
    const float INV = 0.0625f, INV2 = 0.0625f * 0.0625f;
    float tc = fminf(fmaxf(tau[hi], 1.0f), 32.0f);
    float t1 = ((float)(dd + 1) - tc) * INV2;
    float c  = fmaxf(0.0f, INV - fabsf(t1));
    g_cw[i] = c * lateral[hi];

    if (i < BB * NDLY * HH) g_hist[i] = 0.0f;
    if (i < BB) {
        g_tau[i] = 0; g_done[i] = 0; g_stepsA[i] = 0; g_curIdx[i] = -1;
        unsigned o0, o1;
        tf2x32(0u, 42u, 0u, (unsigned)i, o0, o1);
        g_keys[2 * i]     = o0;
        g_keys[2 * i + 1] = o1;
    }
    if (i < 8 * 32) g_cnt1[i] = 0u;
    if (i == 0) { g_cnt2 = 0u; g_phase = 0u; }
}

__global__ void build_aux_kernel(const float* __restrict__ w_aff,
                                 const float* __restrict__ b_aff,
                                 const float* __restrict__ w_eff) {
    int i = blockIdx.x * 256 + threadIdx.x;        // 65536
    int a = i / HH, h2a = i % HH;
    g_wa1[i] = w_aff[h2a * INN + a] + b_aff[h2a];
    if (i < (HH / 2) * VV) {
        int h2 = i / VV, v = i % VV;
        g_weT2[i] = pkf2(w_eff[v * HH + 2 * h2], w_eff[v * HH + 2 * h2 + 1]);
    }
}

// xw[m][h] = sum_i x[m][i]*w_aff[h][i] + b_aff[h]
__global__ __launch_bounds__(256) void xw_gemm_kernel(
        const float* __restrict__ x, const float* __restrict__ w_aff,
        const float* __restrict__ b_aff) {
    __shared__ float As[32][65], Ws[32][65];
    int m0 = blockIdx.x * 64, h0 = blockIdx.y * 64;
    int tid = threadIdx.x, tx = tid % 16, ty = tid / 16;
    float acc[4][4] = {{0}};
    for (int k0 = 0; k0 < INN; k0 += 32) {
        int r = tid >> 2, kq = tid & 3;
#pragma unroll
        for (int j = 0; j < 8; j++) {
            As[kq * 8 + j][r] = x[(size_t)(m0 + r) * INN + k0 + kq * 8 + j];
            Ws[kq * 8 + j][r] = w_aff[(h0 + r) * INN + k0 + kq * 8 + j];
        }
        __syncthreads();
#pragma unroll
        for (int k = 0; k < 32; k++) {
            float av[4], bv[4];
#pragma unroll
            for (int u = 0; u < 4; u++) av[u] = As[k][ty * 4 + u];
#pragma unroll
            for (int v = 0; v < 4; v++) bv[v] = Ws[k][tx * 4 + v];
#pragma unroll
            for (int u = 0; u < 4; u++)
#pragma unroll
                for (int v = 0; v < 4; v++)
                    acc[u][v] = fmaf(av[u], bv[v], acc[u][v]);
        }
        __syncthreads();
    }
#pragma unroll
    for (int u = 0; u < 4; u++)
#pragma unroll
        for (int v = 0; v < 4; v++) {
            int m = m0 + ty * 4 + u, h = h0 + tx * 4 + v;
            g_xw[(size_t)m * HH + h] = acc[u][v] + b_aff[h];
        }
}

// ---------------- persistent step kernel (512 threads) ----------------------
// K1: thread = 1 h-pair x 4 b. A pairs from smem (LDS.64); B via warp-broadcast
// __ldcg float4 from g_hist, prefetched one 4-k chunk ahead. No B smem staging.
__global__ __launch_bounds__(NTHR) void persistent_kernel(
        const int* __restrict__ lengths, const float* __restrict__ b_eff,
        float* __restrict__ out, int N, int writeSteps) {
    extern __shared__ ull dynsmem[];
    ull* Asd = dynsmem;                  // [256 k][32]: hp -> pair {h0+2hp, +1}
    __shared__ int   rowOff[BB];
    __shared__ __align__(16) float sh_hdel[HH];
    __shared__ float parth[2][HH];
    __shared__ float ypart[2][VV];
    __shared__ float sval[VV];
    __shared__ int   sidx[VV];

    int tid = threadIdx.x, cta = blockIdx.x;
    int dd = cta >> 2, hb = cta & 3, h0 = hb * 64;
    int hp = tid & 31, bg = tid >> 5;    // K1: h = h0+2hp,+1 ; b = bg*4..bg*4+3
    int half = tid >> 8, hv = tid & 255; // K2 split

    // one-time: pack cw tile into smem as h-pairs [k][hp]
    {
        const float* cwd = g_cw + (size_t)dd * HH * INN;
        for (int idx = tid; idx < 256 * 32; idx += NTHR) {
            int k = idx >> 5, p = idx & 31;
            int h = h0 + p * 2;
            Asd[idx] = pkf2(cwd[(size_t)h * INN + k], cwd[(size_t)(h + 1) * INN + k]);
        }
    }
    __syncthreads();

    int lenb = (cta < BB) ? lengths[cta] : 0;
    unsigned ph = 0;
    int TS = TT + 9 + N;

    for (int step = 0; step < TS; step++) {
        // ---- K1 ----
        if (tid < BB) {
            int tb = __ldcg(&g_tau[tid]);
            rowOff[tid] = tid * (NDLY * HH) + (((tb - (dd + 1)) & 31) * HH);
        }
        __syncthreads();
        int row0 = rowOff[bg * 4 + 0];
        int row1 = rowOff[bg * 4 + 1];
        int row2 = rowOff[bg * 4 + 2];
        int row3 = rowOff[bg * 4 + 3];
        ull acc0 = 0ull, acc1 = 0ull, acc2 = 0ull, acc3 = 0ull;

        float4 vb0 = __ldcg((const float4*)(g_hist + row0));
        float4 vb1 = __ldcg((const float4*)(g_hist + row1));
        float4 vb2 = __ldcg((const float4*)(g_hist + row2));
        float4 vb3 = __ldcg((const float4*)(g_hist + row3));
#pragma unroll 4
        for (int kc = 0; kc < 64; kc++) {
            float4 nb0, nb1, nb2, nb3;
            if (kc < 63) {
                int off = (kc + 1) * 4;
                nb0 = __ldcg((const float4*)(g_hist + row0 + off));
                nb1 = __ldcg((const float4*)(g_hist + row1 + off));
                nb2 = __ldcg((const float4*)(g_hist + row2 + off));
                nb3 = __ldcg((const float4*)(g_hist + row3 + off));
            }
            const ull* ab = Asd + (size_t)(kc * 4) * 32 + hp;
            ull A0 = ab[0], A1 = ab[32], A2 = ab[64], A3 = ab[96];
            acc0 = ffma2(A0, pkf2(vb0.x, vb0.x), acc0);
            acc1 = ffma2(A0, pkf2(vb1.x, vb1.x), acc1);
            acc2 = ffma2(A0, pkf2(vb2.x, vb2.x), acc2);
            acc3 = ffma2(A0, pkf2(vb3.x, vb3.x), acc3);
            acc0 = ffma2(A1, pkf2(vb0.y, vb0.y), acc0);
            acc1 = ffma2(A1, pkf2(vb1.y, vb1.y), acc1);
            acc2 = ffma2(A1, pkf2(vb2.y, vb2.y), acc2);
            acc3 = ffma2(A1, pkf2(vb3.y, vb3.y), acc3);
            acc0 = ffma2(A2, pkf2(vb0.z, vb0.z), acc0);
            acc1 = ffma2(A2, pkf2(vb1.z, vb1.z), acc1);
            acc2 = ffma2(A2, pkf2(vb2.z, vb2.z), acc2);
            acc3 = ffma2(A2, pkf2(vb3.z, vb3.z), acc3);
            acc0 = ffma2(A3, pkf2(vb0.w, vb0.w), acc0);
            acc1 = ffma2(A3, pkf2(vb1.w, vb1.w), acc1);
            acc2 = ffma2(A3, pkf2(vb2.w, vb2.w), acc2);
            acc3 = ffma2(A3, pkf2(vb3.w, vb3.w), acc3);
            vb0 = nb0; vb1 = nb1; vb2 = nb2; vb3 = nb3;
        }
        {
            float* P = g_partial + (size_t)dd * BH;
            *(float2*)(P + (size_t)(bg * 4 + 0) * HH + h0 + hp * 2) = upkf2(acc0);
            *(float2*)(P + (size_t)(bg * 4 + 1) * HH + h0 + hp * 2) = upkf2(acc1);
            *(float2*)(P + (size_t)(bg * 4 + 2) * HH + h0 + hp * 2) = upkf2(acc2);
            *(float2*)(P + (size_t)(bg * 4 + 3) * HH + h0 + hp * 2) = upkf2(acc3);
        }
        gsync(ph);

        // ---- K2 ----
        if (cta < BB) {
            int b = cta;
            // split partial reduce: half 1 sums s=31..16, half 0 sums 15..0
            {
                float ps = 0.0f;
                int sbase = half * 16;
#pragma unroll
                for (int s = 15; s >= 0; --s)
                    ps += __ldcg(&g_partial[(size_t)(sbase + s) * BH + b * HH + hv]);
                parth[half][hv] = ps;
            }
            __syncthreads();

            if (step < TT) {
                if (tid < HH) {
                    float acc2s = parth[1][tid] + parth[0][tid];
                    int t = step;
                    float hvv = xla_tanh(g_xw[(size_t)(b * TT + t) * HH + tid] + acc2s);
                    if (t < lenb) {
                        g_hist[b * (NDLY * HH) + (t & 31) * HH + tid] = hvv;
                        if (tid == 0) g_tau[b] = t + 1;
                    }
                }
            } else {
                int g = step - TT;
                int ci = g_curIdx[b], myTau = g_tau[b], myDone = g_done[b];
                int mySteps = g_stepsA[b];

                if (tid < HH)
                    sh_hdel[tid] = parth[1][tid] + parth[0][tid];
                __syncthreads();

                // logits matvec split over halves: h2 in [half*64, half*64+64)
                {
                    const ull* hdl = (const ull*)sh_hdel;
                    int h2b = half * 64;
                    ull ya = 0ull, yb = 0ull;
#pragma unroll 8
                    for (int j = 0; j < 64; j += 2) {
                        ya = ffma2(g_weT2[(size_t)(h2b + j) * VV + hv],     hdl[h2b + j],     ya);
                        yb = ffma2(g_weT2[(size_t)(h2b + j + 1) * VV + hv], hdl[h2b + j + 1], yb);
                    }
                    float2 pa = upkf2(ya), pb = upkf2(yb);
                    ypart[half][hv] = (pa.x + pa.y) + (pb.x + pb.y);
                }
                __syncthreads();

                float y = 0.0f;
                if (tid < VV) {
                    y = (ypart[1][tid] + ypart[0][tid]) + b_eff[tid];

                    unsigned kv = (g < 9) ? (unsigned)g : (unsigned)(1000 + (g - 9));
                    unsigned f0, f1;
                    tf2x32(g_keys[2 * b], g_keys[2 * b + 1], 0u, kv, f0, f1);
                    unsigned o0, o1;
                    tf2x32(f0, f1, 0u, (unsigned)tid, o0, o1);
                    unsigned bits = o0 ^ o1;

                    const float TINY = 1.17549435e-38f;
                    float fm = __uint_as_float((bits >> 9) | 0x3F800000u) - 1.0f;
                    float uu = fmaxf(TINY, fm * (1.0f - TINY) + TINY);
                    float gum = -logf(-logf(uu));

                    sval[tid] = y + gum; sidx[tid] = tid;
                }
                __syncthreads();
                for (int off = 128; off > 0; off >>= 1) {
                    if (tid < off) {
                        float v2 = sval[tid + off]; int i2 = sidx[tid + off];
                        if (v2 > sval[tid] || (v2 == sval[tid] && i2 < sidx[tid])) {
                            sval[tid] = v2; sidx[tid] = i2;
                        }
                    }
                    __syncthreads();
                }
                int amax = sidx[0];

                if (tid < HH) {
                    float xin = (ci < 0) ? g_xw[(size_t)(b * TT + (lenb - 1)) * HH + tid]
                                         : g_wa1[ci * HH + tid];
                    float hvv = xla_tanh(xin + sh_hdel[tid]);

                    bool thinkPh = (g < 9);
                    bool adv = thinkPh ? (myDone == 0) : true;
                    if (adv) g_hist[b * (NDLY * HH) + (myTau & 31) * HH + tid] = hvv;

                    if (!thinkPh) {
                        int k = g - 9;
                        if (tid < VV - 1)
                            out[((size_t)b * N + k) * (VV - 1) + tid] = y;
                    }
                    if (tid == 0) {
                        if (thinkPh) {
                            int nst = mySteps + (myDone ? 0 : 1);
                            int nd = (myDone || amax == (VV - 1) || nst > 8) ? 1 : 0;
                            g_stepsA[b] = nst; g_done[b] = nd;
                            if (!myDone) { g_tau[b] = myTau + 1; g_curIdx[b] = amax; }
                            if (g == 8 && writeSteps)
                                out[(size_t)BB * N * (VV - 1) + b] = (float)nst;
                        } else {
                            g_tau[b] = myTau + 1; g_curIdx[b] = amax;
                        }
                    }
                }
            }
        }
        gsync(ph);
    }
}

extern "C" void kernel_launch(void* const* d_in, const int* in_sizes, int n_in,
                              void* d_out, int out_size) {
    const float* x       = (const float*)d_in[0];
    const float* w_aff   = (const float*)d_in[1];
    const float* b_aff   = (const float*)d_in[2];
    const float* lateral = (const float*)d_in[3];
    const float* tau     = (const float*)d_in[4];
    const float* w_eff   = (const float*)d_in[5];
    const float* b_eff   = (const float*)d_in[6];
    const int*   lengths = (const int*)d_in[7];
    (void)n_in; (void)in_sizes;
    float* out = (float*)d_out;

    int Vm1 = VV - 1;
    int N, writeSteps;
    if (out_size % (BB * Vm1) == 0) { N = out_size / (BB * Vm1); writeSteps = 0; }
    else { N = (out_size - BB) / (BB * Vm1); writeSteps = 1; }

    int dynBytes = 256 * 32 * (int)sizeof(ull);   // 65536
    cudaFuncSetAttribute(persistent_kernel,
                         cudaFuncAttributeMaxDynamicSharedMemorySize, dynBytes);

    build_cw_kernel<<<(NDLY * HH * INN) / 256, 256>>>(lateral, tau);
    build_aux_kernel<<<(INN * HH) / 256, 256>>>(w_aff, b_aff, w_eff);
    xw_gemm_kernel<<<dim3((BB * TT) / 64, HH / 64), 256>>>(x, w_aff, b_aff);

    persistent_kernel<<<GRID, NTHR, dynBytes>>>(lengths, b_eff, out, N, writeSteps);
}

// round 15
// speedup vs baseline: 1.3004x; 1.0025x over previous
#include <cuda_runtime.h>

#define BB   64
#define TT   128
#define HH   256
#define INN  256
#define VV   256
#define NDLY 32
#define BH   (BB*HH)
#define GRID 128
#define NTHR 512
typedef unsigned long long ull;

__device__ float    g_cw[NDLY*HH*INN];
__device__ float    g_xw[BB*TT*HH];
__device__ float    g_wa1[INN*HH];
__device__ ull      g_weT2[(HH/2)*VV];     // [h2][v] packed {w[v][2h2], w[v][2h2+1]}
__device__ float    g_hist[BB*NDLY*HH];
__device__ float    g_partial[NDLY*BB*HH];
__device__ unsigned g_keys[2*BB];
__device__ int      g_tau[BB], g_done[BB], g_stepsA[BB], g_curIdx[BB];
__device__ unsigned g_cnt1[8*32];          // 8 group counters, 128B apart
__device__ unsigned g_cnt2;
__device__ unsigned g_phase;

// ---- packed f32x2 helpers ----
__device__ __forceinline__ ull pkf2(float lo, float hi) {
    ull r; asm("mov.b64 %0, {%1, %2};" : "=l"(r) : "f"(lo), "f"(hi)); return r;
}
__device__ __forceinline__ float2 upkf2(ull v) {
    float2 r; asm("mov.b64 {%0, %1}, %2;" : "=f"(r.x), "=f"(r.y) : "l"(v)); return r;
}
__device__ __forceinline__ ull ffma2(ull a, ull b, ull c) {
    ull d; asm("fma.rn.f32x2 %0, %1, %2, %3;" : "=l"(d) : "l"(a), "l"(b), "l"(c));
    return d;
}

// XLA/Eigen f32 tanh
__device__ __forceinline__ float xla_tanh(float x) {
    if (fabsf(x) < 0.0004f) return x;
    float cx = fminf(fmaxf(x, -7.90531110763549805f), 7.90531110763549805f);
    float x2 = cx * cx;
    float p = fmaf(x2, -2.76076847742355e-16f, 2.00018790482477e-13f);
    p = fmaf(x2, p, -8.60467152213735e-11f);
    p = fmaf(x2, p,  5.12229709037114e-08f);
    p = fmaf(x2, p,  1.48572235717979e-05f);
    p = fmaf(x2, p,  6.37261928875436e-04f);
    p = fmaf(x2, p,  4.89352455891786e-03f);
    p = cx * p;
    float q = fmaf(x2, 1.19825839466702e-06f, 1.18534705686654e-04f);
    q = fmaf(x2, q, 2.26843463243900e-03f);
    q = fmaf(x2, q, 4.89352518554385e-03f);
    return p / q;
}

__device__ __forceinline__ void tf2x32(unsigned k0, unsigned k1,
                                       unsigned x0, unsigned x1,
                                       unsigned &o0, unsigned &o1) {
    unsigned ks2 = k0 ^ k1 ^ 0x1BD11BDAu;
    x0 += k0; x1 += k1;
#define TF_R(r) { x0 += x1; x1 = (x1 << (r)) | (x1 >> (32 - (r))); x1 ^= x0; }
    TF_R(13) TF_R(15) TF_R(26) TF_R(6)
    x0 += k1;  x1 += ks2 + 1u;
    TF_R(17) TF_R(29) TF_R(16) TF_R(24)
    x0 += ks2; x1 += k0 + 2u;
    TF_R(13) TF_R(15) TF_R(26) TF_R(6)
    x0 += k0;  x1 += k1 + 3u;
    TF_R(17) TF_R(29) TF_R(16) TF_R(24)
    x0 += k1;  x1 += ks2 + 4u;
    TF_R(13) TF_R(15) TF_R(26) TF_R(6)
    x0 += ks2; x1 += k0 + 5u;
#undef TF_R
    o0 = x0; o1 = x1;
}

// R9-style tree grid barrier (empirically best): relaxed atomics + threadfence
__device__ __forceinline__ void gsync(unsigned &ph) {
    __syncthreads();
    if (threadIdx.x == 0) {
        __threadfence();
        if (atomicAdd(&g_cnt1[(blockIdx.x >> 4) * 32], 1u) == 15u) {
            if (atomicAdd(&g_cnt2, 1u) == 7u) {
                g_cnt2 = 0u;
#pragma unroll
                for (int i = 0; i < 8; i++) g_cnt1[i * 32] = 0u;
                __threadfence();
                *(volatile unsigned*)&g_phase = ph + 1u;
            }
        }
        while (*(volatile unsigned*)&g_phase < ph + 1u) {}
        __threadfence();
    }
    ph++;
    __syncthreads();
}

// setup kernel 1: cw build + state init + PRNG child keys (merged)
__global__ void build_cw_kernel(const float* __restrict__ lateral,
                                const float* __restrict__ tau) {
    int i = blockIdx.x * 256 + threadIdx.x;
    int dd = i >> 16;
    int hi = i & 65535;
    const float INV = 0.0625f, INV2 = 0.0625f * 0.0625f;
    float tc = fminf(fmaxf(tau[hi], 1.0f), 32.0f);
    float t1 = ((float)(dd + 1) - tc) * INV2;
    float c  = fmaxf(0.0f, INV - fabsf(t1));
    g_cw[i] = c * lateral[hi];

    if (i < BB * NDLY * HH) g_hist[i] = 0.0f;
    if (i < BB) {
        g_tau[i] = 0; g_done[i] = 0; g_stepsA[i] = 0; g_curIdx[i] = -1;
        unsigned o0, o1;
        tf2x32(0u, 42u, 0u, (unsigned)i, o0, o1);
        g_keys[2 * i]     = o0;
        g_keys[2 * i + 1] = o1;
    }
    if (i < 8 * 32) g_cnt1[i] = 0u;
    if (i == 0) { g_cnt2 = 0u; g_phase = 0u; }
}

__global__ void build_aux_kernel(const float* __restrict__ w_aff,
                                 const float* __restrict__ b_aff,
                                 const float* __restrict__ w_eff) {
    int i = blockIdx.x * 256 + threadIdx.x;        // 65536
    int a = i / HH, h2a = i % HH;
    g_wa1[i] = w_aff[h2a * INN + a] + b_aff[h2a];
    if (i < (HH / 2) * VV) {
        int h2 = i / VV, v = i % VV;
        g_weT2[i] = pkf2(w_eff[v * HH + 2 * h2], w_eff[v * HH + 2 * h2 + 1]);
    }
}

// xw[m][h] = sum_i x[m][i]*w_aff[h][i] + b_aff[h]
__global__ __launch_bounds__(256) void xw_gemm_kernel(
        const float* __restrict__ x, const float* __restrict__ w_aff,
        const float* __restrict__ b_aff) {
    __shared__ float As[32][65], Ws[32][65];
    int m0 = blockIdx.x * 64, h0 = blockIdx.y * 64;
    int tid = threadIdx.x, tx = tid % 16, ty = tid / 16;
    float acc[4][4] = {{0}};
    for (int k0 = 0; k0 < INN; k0 += 32) {
        int r = tid >> 2, kq = tid & 3;
#pragma unroll
        for (int j = 0; j < 8; j++) {
            As[kq * 8 + j][r] = x[(size_t)(m0 + r) * INN + k0 + kq * 8 + j];
            Ws[kq * 8 + j][r] = w_aff[(h0 + r) * INN + k0 + kq * 8 + j];
        }
        __syncthreads();
#pragma unroll
        for (int k = 0; k < 32; k++) {
            float av[4], bv[4];
#pragma unroll
            for (int u = 0; u < 4; u++) av[u] = As[k][ty * 4 + u];
#pragma unroll
            for (int v = 0; v < 4; v++) bv[v] = Ws[k][tx * 4 + v];
#pragma unroll
            for (int u = 0; u < 4; u++)
#pragma unroll
                for (int v = 0; v < 4; v++)
                    acc[u][v] = fmaf(av[u], bv[v], acc[u][v]);
        }
        __syncthreads();
    }
#pragma unroll
    for (int u = 0; u < 4; u++)
#pragma unroll
        for (int v = 0; v < 4; v++) {
            int m = m0 + ty * 4 + u, h = h0 + tx * 4 + v;
            g_xw[(size_t)m * HH + h] = acc[u][v] + b_aff[h];
        }
}

// consume one 4-k chunk for 4 b rows against A chunk base
#define K1_CHUNK(vb0, vb1, vb2, vb3, abase)                                   \
    {                                                                          \
        const ull* ab = (abase);                                               \
        ull A0 = ab[0], A1 = ab[32], A2 = ab[64], A3 = ab[96];                 \
        acc0 = ffma2(A0, pkf2((vb0).x, (vb0).x), acc0);                        \
        acc1 = ffma2(A0, pkf2((vb1).x, (vb1).x), acc1);                        \
        acc2 = ffma2(A0, pkf2((vb2).x, (vb2).x), acc2);                        \
        acc3 = ffma2(A0, pkf2((vb3).x, (vb3).x), acc3);                        \
        acc0 = ffma2(A1, pkf2((vb0).y, (vb0).y), acc0);                        \
        acc1 = ffma2(A1, pkf2((vb1).y, (vb1).y), acc1);                        \
        acc2 = ffma2(A1, pkf2((vb2).y, (vb2).y), acc2);                        \
        acc3 = ffma2(A1, pkf2((vb3).y, (vb3).y), acc3);                        \
        acc0 = ffma2(A2, pkf2((vb0).z, (vb0).z), acc0);                        \
        acc1 = ffma2(A2, pkf2((vb1).z, (vb1).z), acc1);                        \
        acc2 = ffma2(A2, pkf2((vb2).z, (vb2).z), acc2);                        \
        acc3 = ffma2(A2, pkf2((vb3).z, (vb3).z), acc3);                        \
        acc0 = ffma2(A3, pkf2((vb0).w, (vb0).w), acc0);                        \
        acc1 = ffma2(A3, pkf2((vb1).w, (vb1).w), acc1);                        \
        acc2 = ffma2(A3, pkf2((vb2).w, (vb2).w), acc2);                        \
        acc3 = ffma2(A3, pkf2((vb3).w, (vb3).w), acc3);                        \
    }

// ---------------- persistent step kernel (512 threads) ----------------------
// K1: thread = 1 h-pair x 4 b. A pairs from smem (LDS.64); B via warp-broadcast
// __ldcg float4 from g_hist with DEPTH-2 prefetch (chunk kc+2 in flight while
// consuming kc). No B smem staging.
__global__ __launch_bounds__(NTHR) void persistent_kernel(
        const int* __restrict__ lengths, const float* __restrict__ b_eff,
        float* __restrict__ out, int N, int writeSteps) {
    extern __shared__ ull dynsmem[];
    ull* Asd = dynsmem;                  // [256 k][32]: hp -> pair {h0+2hp, +1}
    __shared__ int   rowOff[BB];
    __shared__ __align__(16) float sh_hdel[HH];
    __shared__ float parth[2][HH];
    __shared__ float ypart[2][VV];
    __shared__ float sval[VV];
    __shared__ int   sidx[VV];

    int tid = threadIdx.x, cta = blockIdx.x;
    int dd = cta >> 2, hb = cta & 3, h0 = hb * 64;
    int hp = tid & 31, bg = tid >> 5;    // K1: h = h0+2hp,+1 ; b = bg*4..bg*4+3
    int half = tid >> 8, hv = tid & 255; // K2 split

    // one-time: pack cw tile into smem as h-pairs [k][hp]
    {
        const float* cwd = g_cw + (size_t)dd * HH * INN;
        for (int idx = tid; idx < 256 * 32; idx += NTHR) {
            int k = idx >> 5, p = idx & 31;
            int h = h0 + p * 2;
            Asd[idx] = pkf2(cwd[(size_t)h * INN + k], cwd[(size_t)(h + 1) * INN + k]);
        }
    }
    __syncthreads();

    int lenb = (cta < BB) ? lengths[cta] : 0;
    unsigned ph = 0;
    int TS = TT + 9 + N;

    for (int step = 0; step < TS; step++) {
        // ---- K1 ----
        if (tid < BB) {
            int tb = __ldcg(&g_tau[tid]);
            rowOff[tid] = tid * (NDLY * HH) + (((tb - (dd + 1)) & 31) * HH);
        }
        __syncthreads();
        int row0 = rowOff[bg * 4 + 0];
        int row1 = rowOff[bg * 4 + 1];
        int row2 = rowOff[bg * 4 + 2];
        int row3 = rowOff[bg * 4 + 3];
        ull acc0 = 0ull, acc1 = 0ull, acc2 = 0ull, acc3 = 0ull;

        // depth-2 pipeline: X = chunk kc, Y = chunk kc+1
        float4 x0 = __ldcg((const float4*)(g_hist + row0));
        float4 x1 = __ldcg((const float4*)(g_hist + row1));
        float4 x2 = __ldcg((const float4*)(g_hist + row2));
        float4 x3 = __ldcg((const float4*)(g_hist + row3));
        float4 y0 = __ldcg((const float4*)(g_hist + row0 + 4));
        float4 y1 = __ldcg((const float4*)(g_hist + row1 + 4));
        float4 y2 = __ldcg((const float4*)(g_hist + row2 + 4));
        float4 y3 = __ldcg((const float4*)(g_hist + row3 + 4));
#pragma unroll 2
        for (int kc = 0; kc < 64; kc += 2) {
            float4 n0, n1, n2, n3;
            if (kc + 2 < 64) {
                int off = (kc + 2) * 4;
                n0 = __ldcg((const float4*)(g_hist + row0 + off));
                n1 = __ldcg((const float4*)(g_hist + row1 + off));
                n2 = __ldcg((const float4*)(g_hist + row2 + off));
                n3 = __ldcg((const float4*)(g_hist + row3 + off));
            }
            K1_CHUNK(x0, x1, x2, x3, Asd + (size_t)(kc * 4) * 32 + hp);
            x0 = n0; x1 = n1; x2 = n2; x3 = n3;

            float4 m0, m1, m2, m3;
            if (kc + 3 < 64) {
                int off = (kc + 3) * 4;
                m0 = __ldcg((const float4*)(g_hist + row0 + off));
                m1 = __ldcg((const float4*)(g_hist + row1 + off));
                m2 = __ldcg((const float4*)(g_hist + row2 + off));
                m3 = __ldcg((const float4*)(g_hist + row3 + off));
            }
            K1_CHUNK(y0, y1, y2, y3, Asd + (size_t)((kc + 1) * 4) * 32 + hp);
            y0 = m0; y1 = m1; y2 = m2; y3 = m3;
        }
        {
            float* P = g_partial + (size_t)dd * BH;
            *(float2*)(P + (size_t)(bg * 4 + 0) * HH + h0 + hp * 2) = upkf2(acc0);
            *(float2*)(P + (size_t)(bg * 4 + 1) * HH + h0 + hp * 2) = upkf2(acc1);
            *(float2*)(P + (size_t)(bg * 4 + 2) * HH + h0 + hp * 2) = upkf2(acc2);
            *(float2*)(P + (size_t)(bg * 4 + 3) * HH + h0 + hp * 2) = upkf2(acc3);
        }
        gsync(ph);

        // ---- K2 ----
        if (cta < BB) {
            int b = cta;
            // split partial reduce: half 1 sums s=31..16, half 0 sums 15..0
            {
                float ps = 0.0f;
                int sbase = half * 16;
#pragma unroll
                for (int s = 15; s >= 0; --s)
                    ps += __ldcg(&g_partial[(size_t)(sbase + s) * BH + b * HH + hv]);
                parth[half][hv] = ps;
            }
            __syncthreads();

            if (step < TT) {
                if (tid < HH) {
                    float acc2s = parth[1][tid] + parth[0][tid];
                    int t = step;
                    float hvv = xla_tanh(g_xw[(size_t)(b * TT + t) * HH + tid] + acc2s);
                    if (t < lenb) {
                        g_hist[b * (NDLY * HH) + (t & 31) * HH + tid] = hvv;
                        if (tid == 0) g_tau[b] = t + 1;
                    }
                }
            } else {
                int g = step - TT;
                int ci = g_curIdx[b], myTau = g_tau[b], myDone = g_done[b];
                int mySteps = g_stepsA[b];

                if (tid < HH)
                    sh_hdel[tid] = parth[1][tid] + parth[0][tid];
                __syncthreads();

                // logits matvec split over halves: h2 in [half*64, half*64+64)
                {
                    const ull* hdl = (const ull*)sh_hdel;
                    int h2b = half * 64;
                    ull ya = 0ull, yb = 0ull;
#pragma unroll 4
                    for (int j = 0; j < 64; j += 2) {
                        ya = ffma2(g_weT2[(size_t)(h2b + j) * VV + hv],     hdl[h2b + j],     ya);
                        yb = ffma2(g_weT2[(size_t)(h2b + j + 1) * VV + hv], hdl[h2b + j + 1], yb);
                    }
                    float2 pa = upkf2(ya), pb = upkf2(yb);
                    ypart[half][hv] = (pa.x + pa.y) + (pb.x + pb.y);
                }
                __syncthreads();

                float y = 0.0f;
                if (tid < VV) {
                    y = (ypart[1][tid] + ypart[0][tid]) + b_eff[tid];

                    unsigned kv = (g < 9) ? (unsigned)g : (unsigned)(1000 + (g - 9));
                    unsigned f0, f1;
                    tf2x32(g_keys[2 * b], g_keys[2 * b + 1], 0u, kv, f0, f1);
                    unsigned o0, o1;
                    tf2x32(f0, f1, 0u, (unsigned)tid, o0, o1);
                    unsigned bits = o0 ^ o1;

                    const float TINY = 1.17549435e-38f;
                    float fm = __uint_as_float((bits >> 9) | 0x3F800000u) - 1.0f;
                    float uu = fmaxf(TINY, fm * (1.0f - TINY) + TINY);
                    float gum = -logf(-logf(uu));

                    sval[tid] = y + gum; sidx[tid] = tid;
                }
                __syncthreads();
                for (int off = 128; off > 0; off >>= 1) {
                    if (tid < off) {
                        float v2 = sval[tid + off]; int i2 = sidx[tid + off];
                        if (v2 > sval[tid] || (v2 == sval[tid] && i2 < sidx[tid])) {
                            sval[tid] = v2; sidx[tid] = i2;
                        }
                    }
                    __syncthreads();
                }
                int amax = sidx[0];

                if (tid < HH) {
                    float xin = (ci < 0) ? g_xw[(size_t)(b * TT + (lenb - 1)) * HH + tid]
                                         : g_wa1[ci * HH + tid];
                    float hvv = xla_tanh(xin + sh_hdel[tid]);

                    bool thinkPh = (g < 9);
                    bool adv = thinkPh ? (myDone == 0) : true;
                    if (adv) g_hist[b * (NDLY * HH) + (myTau & 31) * HH + tid] = hvv;

                    if (!thinkPh) {
                        int k = g - 9;
                        if (tid < VV - 1)
                            out[((size_t)b * N + k) * (VV - 1) + tid] = y;
                    }
                    if (tid == 0) {
                        if (thinkPh) {
                            int nst = mySteps + (myDone ? 0 : 1);
                            int nd = (myDone || amax == (VV - 1) || nst > 8) ? 1 : 0;
                            g_stepsA[b] = nst; g_done[b] = nd;
                            if (!myDone) { g_tau[b] = myTau + 1; g_curIdx[b] = amax; }
                            if (g == 8 && writeSteps)
                                out[(size_t)BB * N * (VV - 1) + b] = (float)nst;
                        } else {
                            g_tau[b] = myTau + 1; g_curIdx[b] = amax;
                        }
                    }
                }
            }
        }
        gsync(ph);
    }
}

extern "C" void kernel_launch(void* const* d_in, const int* in_sizes, int n_in,
                              void* d_out, int out_size) {
    const float* x       = (const float*)d_in[0];
    const float* w_aff   = (const float*)d_in[1];
    const float* b_aff   = (const float*)d_in[2];
    const float* lateral = (const float*)d_in[3];
    const float* tau     = (const float*)d_in[4];
    const float* w_eff   = (const float*)d_in[5];
    const float* b_eff   = (const float*)d_in[6];
    const int*   lengths = (const int*)d_in[7];
    (void)n_in; (void)in_sizes;
    float* out = (float*)d_out;

    int Vm1 = VV - 1;
    int N, writeSteps;
    if (out_size % (BB * Vm1) == 0) { N = out_size / (BB * Vm1); writeSteps = 0; }
    else { N = (out_size - BB) / (BB * Vm1); writeSteps = 1; }

    int dynBytes = 256 * 32 * (int)sizeof(ull);   // 65536
    cudaFuncSetAttribute(persistent_kernel,
                         cudaFuncAttributeMaxDynamicSharedMemorySize, dynBytes);

    build_cw_kernel<<<(NDLY * HH * INN) / 256, 256>>>(lateral, tau);
    build_aux_kernel<<<(INN * HH) / 256, 256>>>(w_aff, b_aff, w_eff);
    xw_gemm_kernel<<<dim3((BB * TT) / 64, HH / 64), 256>>>(x, w_aff, b_aff);

    persistent_kernel<<<GRID, NTHR, dynBytes>>>(lengths, b_eff, out, N, writeSteps);
}